// round 15
// baseline (speedup 1.0000x reference)
#include <cuda_runtime.h>
#include <cuda_fp16.h>
#include <cstdint>
#include <math.h>

// ---------------------------------------------------------------------------
// Problem: x[4,2048,1024] f32; W_qkv[1024,3072]; W_o[1024,1024]; out[4,2048,1024]
//   1) convert x -> A' fp16 [8192, 1024]  (vectorized)
//   2) transpose W_qkv -> B' fp16 [3072, 1024]
//   3) HMMA fp16 GEMM (BK=64, PIPE=2) -> g_qkv (fp16)
//   4) fp16 mma attention (R14 kernel) -> fp16 A'
//   5) transpose W_o -> B'
//   6) HMMA fp16 GEMM -> out (f32)
// ---------------------------------------------------------------------------
#define BB 4
#define NN 2048
#define DD 1024
#define HH 16
#define EE 64
#define MTOT (BB * NN)   // 8192
#define KPA  1024
#define KPB  1024
#define SA   72          // gemm smem row stride in fp16 (64 data + 8 pad)
#define NSTAGE 16        // KPA / 64
#define PIPE 2

__device__ __half g_qkv[MTOT * 3 * DD];
__device__ __half g_A[MTOT * KPA];
__device__ __half g_B[3 * DD * KPB];

// ===========================================================================
__device__ __forceinline__ uint32_t smem_u32(const void* p) {
    uint32_t a;
    asm("{ .reg .u64 t; cvta.to.shared.u64 t, %1; cvt.u32.u64 %0, t; }"
        : "=r"(a) : "l"(p));
    return a;
}
__device__ __forceinline__ void cp_async16(uint32_t dst, const void* src) {
    asm volatile("cp.async.cg.shared.global [%0], [%1], 16;"
                 :: "r"(dst), "l"(src) : "memory");
}
__device__ __forceinline__ void ldsm_x4(uint32_t* r, uint32_t addr) {
    asm volatile("ldmatrix.sync.aligned.m8n8.x4.shared.b16 {%0,%1,%2,%3}, [%4];"
                 : "=r"(r[0]), "=r"(r[1]), "=r"(r[2]), "=r"(r[3]) : "r"(addr));
}
__device__ __forceinline__ void ldsm_x4_t(uint32_t* r, uint32_t addr) {
    asm volatile("ldmatrix.sync.aligned.m8n8.x4.trans.shared.b16 {%0,%1,%2,%3}, [%4];"
                 : "=r"(r[0]), "=r"(r[1]), "=r"(r[2]), "=r"(r[3]) : "r"(addr));
}
__device__ __forceinline__ void mma_f16(float* d, const uint32_t* a, const uint32_t* b) {
    asm volatile(
        "mma.sync.aligned.m16n8k16.row.col.f32.f16.f16.f32 "
        "{%0,%1,%2,%3}, {%4,%5,%6,%7}, {%8,%9}, {%0,%1,%2,%3};"
        : "+f"(d[0]), "+f"(d[1]), "+f"(d[2]), "+f"(d[3])
        : "r"(a[0]), "r"(a[1]), "r"(a[2]), "r"(a[3]), "r"(b[0]), "r"(b[1]));
}
__device__ __forceinline__ uint32_t f2h2(float lo, float hi) {
    __half2 p = __floats2half2_rn(lo, hi);
    return *reinterpret_cast<uint32_t*>(&p);
}

// ===========================================================================
// HMMA fp16 GEMM: C[M,Nn] = A'[M,1024] @ B'[Nn,1024]^T, OutT in {float,__half}
// CTA 128x128, 8 warps of 64x32, BK=64, 2-stage (double-buffer) cp.async.
// ===========================================================================
#define BUFB (128 * SA * 2)                  // 18432 B per matrix per stage
#define SMEM_GEMM (PIPE * 2 * BUFB)          // 73728

template <typename OutT>
__global__ __launch_bounds__(256, 2)
void gemm_hmma(const __half* __restrict__ A,
               const __half* __restrict__ B,
               OutT* __restrict__ C, int M, int Nn) {
    extern __shared__ __half smhf[];
    const int tid  = threadIdx.x;
    const int wid  = tid >> 5;
    const int lane = tid & 31;
    const int m0 = blockIdx.y * 128;
    const int n0 = blockIdx.x * 128;
    const int wm = (wid >> 2) * 64;
    const int wn = (wid & 3) * 32;

    const uint32_t sbase = smem_u32(smhf);
    const uint32_t aoff0 = sbase;
    const uint32_t boff0 = sbase + PIPE * BUFB;

    const __half* Ag = A + (size_t)m0 * KPA;
    const __half* Bg = B + (size_t)n0 * KPB;

    // each thread: row tid/2, four 16B chunks (half of 64 cols) for A and B
    const int lr  = tid >> 1;
    const int lcb = (tid & 1) * 4;

    auto load_stage = [&](int s) {
        const int buf = s & 1;
        const uint32_t ab = aoff0 + buf * BUFB;
        const uint32_t bb = boff0 + buf * BUFB;
        const int k0 = s * 64;
        const __half* arow = Ag + (size_t)lr * KPA + k0;
        const __half* brow = Bg + (size_t)lr * KPB + k0;
#pragma unroll
        for (int c = 0; c < 4; c++) {
            const int kc = lcb + c;
            const uint32_t doff = (uint32_t)(lr * SA + kc * 8) * 2;
            cp_async16(ab + doff, arow + kc * 8);
            cp_async16(bb + doff, brow + kc * 8);
        }
        asm volatile("cp.async.commit_group;" ::: "memory");
    };

    float acc[4][4][4];
#pragma unroll
    for (int i = 0; i < 4; i++)
#pragma unroll
        for (int j = 0; j < 4; j++)
#pragma unroll
            for (int k = 0; k < 4; k++) acc[i][j][k] = 0.0f;

    const int arow  = wm + (lane & 15);
    const int akoff = (lane >> 4) * 8;
    const int brow  = wn + (lane >> 4) * 8 + (lane & 7);
    const int bkoff = ((lane >> 3) & 1) * 8;

    load_stage(0);

    for (int s = 0; s < NSTAGE; s++) {
        asm volatile("cp.async.wait_group 0;" ::: "memory");
        __syncthreads();
        if (s + 1 < NSTAGE) load_stage(s + 1);

        const int buf = s & 1;
        const uint32_t ab = aoff0 + buf * BUFB;
        const uint32_t bb = boff0 + buf * BUFB;

#pragma unroll
        for (int ksub = 0; ksub < 4; ksub++) {
            uint32_t af[4][4], bf[2][4];
#pragma unroll
            for (int mt = 0; mt < 4; mt++)
                ldsm_x4(af[mt], ab + (uint32_t)((arow + mt * 16) * SA + ksub * 16 + akoff) * 2);
#pragma unroll
            for (int p = 0; p < 2; p++)
                ldsm_x4(bf[p], bb + (uint32_t)((brow + p * 16) * SA + ksub * 16 + bkoff) * 2);
#pragma unroll
            for (int mt = 0; mt < 4; mt++) {
#pragma unroll
                for (int nt = 0; nt < 4; nt++)
                    mma_f16(acc[mt][nt], af[mt], &bf[nt >> 1][(nt & 1) * 2]);
            }
        }
        __syncthreads();   // all warps done reading buf before it's reloaded
    }

    const int grp = lane >> 2;
    const int tig = lane & 3;
#pragma unroll
    for (int mt = 0; mt < 4; mt++) {
#pragma unroll
        for (int nt = 0; nt < 4; nt++) {
            const int row = m0 + wm + mt * 16 + grp;
            const int col = n0 + wn + nt * 8 + tig * 2;
            if constexpr (sizeof(OutT) == 2) {
                uint32_t v0 = f2h2(acc[mt][nt][0], acc[mt][nt][1]);
                uint32_t v1 = f2h2(acc[mt][nt][2], acc[mt][nt][3]);
                *(uint32_t*)&C[(size_t)row * Nn + col]       = v0;
                *(uint32_t*)&C[(size_t)(row + 8) * Nn + col] = v1;
            } else {
                float2 v0 = make_float2(acc[mt][nt][0], acc[mt][nt][1]);
                float2 v1 = make_float2(acc[mt][nt][2], acc[mt][nt][3]);
                *(float2*)&C[(size_t)row * Nn + col]       = v0;
                *(float2*)&C[(size_t)(row + 8) * Nn + col] = v1;
            }
        }
    }
}

// ===========================================================================
// Conversion kernels
// ===========================================================================
__global__ __launch_bounds__(256)
void convert_rows(const float* __restrict__ in, __half* __restrict__ out, int total8) {
    int idx = blockIdx.x * 256 + threadIdx.x;   // one per 8 elements
    if (idx >= total8) return;
    const float4 v0 = *(const float4*)(in + idx * 8);
    const float4 v1 = *(const float4*)(in + idx * 8 + 4);
    uint32_t hw[4];
    hw[0] = f2h2(v0.x, v0.y);
    hw[1] = f2h2(v0.z, v0.w);
    hw[2] = f2h2(v1.x, v1.y);
    hw[3] = f2h2(v1.z, v1.w);
    *(uint4*)(out + idx * 8) = *(uint4*)hw;
}

__global__ __launch_bounds__(256)
void transpose_h(const float* __restrict__ W, __half* __restrict__ out, int Nw) {
    __shared__ float t[32][33];
    int n0 = blockIdx.x * 32, k0 = blockIdx.y * 32;
    int tx = threadIdx.x, ty = threadIdx.y;
#pragma unroll
    for (int i = ty; i < 32; i += 8)
        t[i][tx] = W[(size_t)(k0 + i) * Nw + n0 + tx];
    __syncthreads();
#pragma unroll
    for (int i = ty; i < 32; i += 8) {
        int n = n0 + i, k = k0 + tx;
        out[(size_t)n * KPB + k] = __float2half_rn(t[tx][i]);
    }
}

// ===========================================================================
// Attention — exact R14 kernel (measured 160us)
// ===========================================================================
#define AT_I 128
#define AT_J 64
#define HSTR 72
#define KBUF (AT_I * HSTR)
#define QBUF (AT_J * HSTR)
#define VBUF (AT_J * HSTR)
#define SMEM_ATTN ((KBUF + 2 * QBUF + 2 * VBUF) * 2)

__global__ __launch_bounds__(256, 2)
void attn_tc(const __half* __restrict__ qkv, __half* __restrict__ Aout) {
    extern __shared__ __half smh[];
    __half* Ksm = smh;

    const uint32_t sbase = smem_u32(smh);
    const uint32_t koff  = sbase;
    const uint32_t q2off = sbase + (uint32_t)KBUF * 2;
    const uint32_t v2off = q2off + (uint32_t)(2 * QBUF) * 2;

    const int it = blockIdx.x;
    const int bh = blockIdx.y;
    const int b = bh >> 4, h = bh & 15;
    const int i0 = it * AT_I;

    const int tid  = threadIdx.x;
    const int wid  = tid >> 5;
    const int lane = tid & 31;
    const int g = lane >> 2;
    const int t = lane & 3;
    const int wm = wid * 16;

    const size_t RS = 3 * DD;
    const __half* Qg = qkv + h * EE;
    const __half* Kg = qkv + DD + h * EE;
    const __half* Vg = qkv + 2 * DD + h * EE;

    const int jt0 = it * 2;
    const int nJT = NN / AT_J;

    auto prefetch_qv = [&](int jt, int buf) {
        const int j0 = jt * AT_J;
#pragma unroll
        for (int i = 0; i < 2; i++) {
            int idx = i * 256 + tid;
            int r = idx >> 3;
            int c = idx & 7;
            const __half* qsrc = Qg + (size_t)(b * NN + j0 + r) * RS + c * 8;
            const __half* vsrc = Vg + (size_t)(b * NN + j0 + r) * RS + c * 8;
            cp_async16(q2off + (uint32_t)(buf * QBUF + r * HSTR + c * 8) * 2, qsrc);
            cp_async16(v2off + (uint32_t)(buf * VBUF + r * HSTR + c * 8) * 2, vsrc);
        }
        asm volatile("cp.async.commit_group;" ::: "memory");
    };

    prefetch_qv(jt0, 0);

#pragma unroll
    for (int i = 0; i < 4; i++) {
        int idx = i * 256 + tid;
        int r = idx >> 3;
        int c = idx & 7;
        cp_async16(koff + (uint32_t)(r * HSTR + c * 8) * 2,
                   Kg + (size_t)(b * NN + i0 + r) * RS + c * 8);
    }
    asm volatile("cp.async.commit_group;" ::: "memory");

    float m0 = -1e30f, m1 = -1e30f, l0 = 0.0f, l1 = 0.0f;
    float O[8][4];
#pragma unroll
    for (int nt = 0; nt < 8; nt++)
#pragma unroll
        for (int k = 0; k < 4; k++) O[nt][k] = 0.0f;

    const int r0g = i0 + wm + g;
    const int r1g = r0g + 8;

    const int a_row  = wm + (lane & 15);
    const int a_koff = (lane >> 4) * 8;
    const int b_row  = (lane >> 4) * 8 + (lane & 7);
    const int b_koff = ((lane >> 3) & 1) * 8;
    const int v_row  = lane & 15;
    const int v_eoff = (lane >> 4) * 8;

    for (int jt = jt0; jt < nJT; jt++) {
        const int j0 = jt * AT_J;
        const int buf = (jt - jt0) & 1;

        asm volatile("cp.async.wait_group 0;" ::: "memory");
        __syncthreads();
        if (jt + 1 < nJT) prefetch_qv(jt + 1, buf ^ 1);

        const uint32_t qb = q2off + (uint32_t)(buf * QBUF) * 2;
        const uint32_t vb = v2off + (uint32_t)(buf * VBUF) * 2;

        float C[8][4];
#pragma unroll
        for (int nt = 0; nt < 8; nt++)
#pragma unroll
            for (int k = 0; k < 4; k++) C[nt][k] = 0.0f;

#pragma unroll
        for (int kt = 0; kt < 4; kt++) {
            uint32_t af[4];
            ldsm_x4(af, koff + (uint32_t)(a_row * HSTR + kt * 16 + a_koff) * 2);
            uint32_t qf[4][4];
#pragma unroll
            for (int p = 0; p < 4; p++)
                ldsm_x4(qf[p], qb + (uint32_t)((p * 16 + b_row) * HSTR + kt * 16 + b_koff) * 2);
#pragma unroll
            for (int nt = 0; nt < 8; nt++)
                mma_f16(C[nt], af, &qf[nt >> 1][(nt & 1) * 2]);
        }

        const bool needmask = (j0 < i0 + AT_I);
        float rmax0 = -1e30f, rmax1 = -1e30f;
#pragma unroll
        for (int nt = 0; nt < 8; nt++) {
            C[nt][0] *= 0.125f; C[nt][1] *= 0.125f;
            C[nt][2] *= 0.125f; C[nt][3] *= 0.125f;
            if (needmask) {
                int c0 = j0 + nt * 8 + 2 * t;
                int c1 = c0 + 1;
                if (c0 < r0g) C[nt][0] = -1e30f;
                if (c1 < r0g) C[nt][1] = -1e30f;
                if (c0 < r1g) C[nt][2] = -1e30f;
                if (c1 < r1g) C[nt][3] = -1e30f;
            }
            rmax0 = fmaxf(rmax0, fmaxf(C[nt][0], C[nt][1]));
            rmax1 = fmaxf(rmax1, fmaxf(C[nt][2], C[nt][3]));
        }
        rmax0 = fmaxf(rmax0, __shfl_xor_sync(0xffffffffu, rmax0, 1));
        rmax0 = fmaxf(rmax0, __shfl_xor_sync(0xffffffffu, rmax0, 2));
        rmax1 = fmaxf(rmax1, __shfl_xor_sync(0xffffffffu, rmax1, 1));
        rmax1 = fmaxf(rmax1, __shfl_xor_sync(0xffffffffu, rmax1, 2));

        float mn0 = fmaxf(m0, rmax0), mn1 = fmaxf(m1, rmax1);
        float sc0 = __expf(m0 - mn0), sc1 = __expf(m1 - mn1);
        m0 = mn0; m1 = mn1;

        float rs0 = 0.0f, rs1 = 0.0f;
#pragma unroll
        for (int nt = 0; nt < 8; nt++) {
            C[nt][0] = __expf(C[nt][0] - mn0);
            C[nt][1] = __expf(C[nt][1] - mn0);
            C[nt][2] = __expf(C[nt][2] - mn1);
            C[nt][3] = __expf(C[nt][3] - mn1);
            rs0 += C[nt][0] + C[nt][1];
            rs1 += C[nt][2] + C[nt][3];
        }
        rs0 += __shfl_xor_sync(0xffffffffu, rs0, 1);
        rs0 += __shfl_xor_sync(0xffffffffu, rs0, 2);
        rs1 += __shfl_xor_sync(0xffffffffu, rs1, 1);
        rs1 += __shfl_xor_sync(0xffffffffu, rs1, 2);
        l0 = l0 * sc0 + rs0;
        l1 = l1 * sc1 + rs1;
#pragma unroll
        for (int nt = 0; nt < 8; nt++) {
            O[nt][0] *= sc0; O[nt][1] *= sc0;
            O[nt][2] *= sc1; O[nt][3] *= sc1;
        }

#pragma unroll
        for (int kt = 0; kt < 4; kt++) {
            uint32_t a[4];
            a[0] = f2h2(C[2 * kt][0],     C[2 * kt][1]);
            a[1] = f2h2(C[2 * kt][2],     C[2 * kt][3]);
            a[2] = f2h2(C[2 * kt + 1][0], C[2 * kt + 1][1]);
            a[3] = f2h2(C[2 * kt + 1][2], C[2 * kt + 1][3]);
#pragma unroll
            for (int e0 = 0; e0 < 64; e0 += 16) {
                uint32_t vf[4];
                ldsm_x4_t(vf, vb + (uint32_t)((kt * 16 + v_row) * HSTR + e0 + v_eoff) * 2);
                mma_f16(O[e0 >> 3],       a, &vf[0]);
                mma_f16(O[(e0 >> 3) + 1], a, &vf[2]);
            }
        }
        __syncthreads();
    }

    {
        float inv0 = 1.0f / l0, inv1 = 1.0f / l1;
#pragma unroll
        for (int nt = 0; nt < 8; nt++) {
            int col = nt * 8 + 2 * t;
            *(uint32_t*)&Ksm[(wm + g)     * HSTR + col] = f2h2(O[nt][0] * inv0, O[nt][1] * inv0);
            *(uint32_t*)&Ksm[(wm + g + 8) * HSTR + col] = f2h2(O[nt][2] * inv1, O[nt][3] * inv1);
        }
    }
    __syncthreads();

#pragma unroll
    for (int itr = 0; itr < 4; itr++) {
        int idx = itr * 256 + tid;
        int r  = idx >> 3;
        int c8 = (idx & 7) << 3;
        uint4 v = *(const uint4*)&Ksm[r * HSTR + c8];
        __half* dst = Aout + (size_t)(b * NN + i0 + r) * KPA + h * EE + c8;
        *(uint4*)dst = v;
    }
}

// ===========================================================================
extern "C" void kernel_launch(void* const* d_in, const int* in_sizes, int n_in,
                              void* d_out, int out_size) {
    const float* x    = (const float*)d_in[0];
    const float* Wqkv = (const float*)d_in[1];
    const float* Wo   = (const float*)d_in[2];
    float* out = (float*)d_out;

    __half* qkv = nullptr;
    __half* Abuf = nullptr;  __half* Bbuf = nullptr;
    cudaGetSymbolAddress((void**)&qkv,  g_qkv);
    cudaGetSymbolAddress((void**)&Abuf, g_A);
    cudaGetSymbolAddress((void**)&Bbuf, g_B);

    cudaFuncSetAttribute(gemm_hmma<__half>, cudaFuncAttributeMaxDynamicSharedMemorySize, SMEM_GEMM);
    cudaFuncSetAttribute(gemm_hmma<float>,  cudaFuncAttributeMaxDynamicSharedMemorySize, SMEM_GEMM);
    cudaFuncSetAttribute(attn_tc, cudaFuncAttributeMaxDynamicSharedMemorySize, SMEM_ATTN);

    // 1) x -> A' fp16 (vectorized, 8 elems/thread)
    convert_rows<<<(MTOT * DD / 8 + 255) / 256, 256>>>(x, Abuf, MTOT * DD / 8);
    // 2) W_qkv -> B' fp16 transpose
    transpose_h<<<dim3(3 * DD / 32, DD / 32), dim3(32, 8)>>>(Wqkv, Bbuf, 3 * DD);
    // 3) QKV GEMM -> fp16 qkv
    gemm_hmma<__half><<<dim3(3 * DD / 128, MTOT / 128), 256, SMEM_GEMM>>>(Abuf, Bbuf, qkv, MTOT, 3 * DD);
    // 4) attention (fp16 mma) -> fp16 A'
    attn_tc<<<dim3(NN / AT_I, BB * HH), 256, SMEM_ATTN>>>(qkv, Abuf);
    // 5) W_o -> B'
    transpose_h<<<dim3(DD / 32, DD / 32), dim3(32, 8)>>>(Wo, Bbuf, DD);
    // 6) O-proj GEMM -> f32 out
    gemm_hmma<float><<<dim3(DD / 128, MTOT / 128), 256, SMEM_GEMM>>>(Abuf, Bbuf, out, MTOT, DD);
}

// round 16
// speedup vs baseline: 1.0493x; 1.0493x over previous
#include <cuda_runtime.h>
#include <cuda_fp16.h>
#include <cstdint>
#include <math.h>

// ---------------------------------------------------------------------------
// Problem: x[4,2048,1024] f32; W_qkv[1024,3072]; W_o[1024,1024]; out[4,2048,1024]
//   1) convert x -> A' fp16 [8192, 1024]  (vectorized)
//   2) transpose W_qkv -> B' fp16 [3072, 1024]
//   3) HMMA fp16 GEMM (R14 config: BK=32, PIPE=3) -> g_qkv (fp16)
//   4) fp16 mma attention, h2exp2 softmax fused into P frags -> fp16 A'
//   5) transpose W_o -> B'
//   6) HMMA fp16 GEMM -> out (f32)
// ---------------------------------------------------------------------------
#define BB 4
#define NN 2048
#define DD 1024
#define HH 16
#define EE 64
#define MTOT (BB * NN)   // 8192
#define KPA  1024
#define KPB  1024
#define SA   40          // gemm smem row stride in fp16 (32 data + 8 pad)
#define NSTAGE 32        // KPA / 32
#define PIPE 3

__device__ __half g_qkv[MTOT * 3 * DD];
__device__ __half g_A[MTOT * KPA];
__device__ __half g_B[3 * DD * KPB];

// ===========================================================================
__device__ __forceinline__ uint32_t smem_u32(const void* p) {
    uint32_t a;
    asm("{ .reg .u64 t; cvta.to.shared.u64 t, %1; cvt.u32.u64 %0, t; }"
        : "=r"(a) : "l"(p));
    return a;
}
__device__ __forceinline__ void cp_async16(uint32_t dst, const void* src) {
    asm volatile("cp.async.cg.shared.global [%0], [%1], 16;"
                 :: "r"(dst), "l"(src) : "memory");
}
__device__ __forceinline__ void ldsm_x4(uint32_t* r, uint32_t addr) {
    asm volatile("ldmatrix.sync.aligned.m8n8.x4.shared.b16 {%0,%1,%2,%3}, [%4];"
                 : "=r"(r[0]), "=r"(r[1]), "=r"(r[2]), "=r"(r[3]) : "r"(addr));
}
__device__ __forceinline__ void ldsm_x4_t(uint32_t* r, uint32_t addr) {
    asm volatile("ldmatrix.sync.aligned.m8n8.x4.trans.shared.b16 {%0,%1,%2,%3}, [%4];"
                 : "=r"(r[0]), "=r"(r[1]), "=r"(r[2]), "=r"(r[3]) : "r"(addr));
}
__device__ __forceinline__ void mma_f16(float* d, const uint32_t* a, const uint32_t* b) {
    asm volatile(
        "mma.sync.aligned.m16n8k16.row.col.f32.f16.f16.f32 "
        "{%0,%1,%2,%3}, {%4,%5,%6,%7}, {%8,%9}, {%0,%1,%2,%3};"
        : "+f"(d[0]), "+f"(d[1]), "+f"(d[2]), "+f"(d[3])
        : "r"(a[0]), "r"(a[1]), "r"(a[2]), "r"(a[3]), "r"(b[0]), "r"(b[1]));
}
__device__ __forceinline__ uint32_t f2h2(float lo, float hi) {
    __half2 p = __floats2half2_rn(lo, hi);
    return *reinterpret_cast<uint32_t*>(&p);
}
__device__ __forceinline__ uint32_t h2u(__half2 p) {
    return *reinterpret_cast<uint32_t*>(&p);
}

// ===========================================================================
// HMMA fp16 GEMM — exact R14 config (BK=32, 3-stage cp.async, 8 warps 64x32)
// ===========================================================================
#define BUFB (128 * SA * 2)
#define SMEM_GEMM (PIPE * 2 * BUFB)

template <typename OutT>
__global__ __launch_bounds__(256, 2)
void gemm_hmma(const __half* __restrict__ A,
               const __half* __restrict__ B,
               OutT* __restrict__ C, int M, int Nn) {
    extern __shared__ __half smhf[];
    const int tid  = threadIdx.x;
    const int wid  = tid >> 5;
    const int lane = tid & 31;
    const int m0 = blockIdx.y * 128;
    const int n0 = blockIdx.x * 128;
    const int wm = (wid >> 2) * 64;
    const int wn = (wid & 3) * 32;

    const uint32_t sbase = smem_u32(smhf);
    const uint32_t aoff0 = sbase;
    const uint32_t boff0 = sbase + PIPE * BUFB;

    const __half* Ag = A + (size_t)m0 * KPA;
    const __half* Bg = B + (size_t)n0 * KPB;

    const int lr  = tid >> 1;
    const int lkc = (tid & 1) * 2;

    auto load_stage = [&](int s) {
        const int buf = s % PIPE;
        const uint32_t ab = aoff0 + buf * BUFB;
        const uint32_t bb = boff0 + buf * BUFB;
        const int k0 = s * 32;
#pragma unroll
        for (int j = 0; j < 2; j++) {
            const int kc = lkc + j;
            const uint32_t doff = (uint32_t)(lr * SA + kc * 8) * 2;
            cp_async16(ab + doff, Ag + (size_t)lr * KPA + k0 + kc * 8);
            cp_async16(bb + doff, Bg + (size_t)lr * KPB + k0 + kc * 8);
        }
        asm volatile("cp.async.commit_group;" ::: "memory");
    };

    float acc[4][4][4];
#pragma unroll
    for (int i = 0; i < 4; i++)
#pragma unroll
        for (int j = 0; j < 4; j++)
#pragma unroll
            for (int k = 0; k < 4; k++) acc[i][j][k] = 0.0f;

    const int arow  = wm + (lane & 15);
    const int akoff = (lane >> 4) * 8;
    const int brow  = wn + (lane >> 4) * 8 + (lane & 7);
    const int bkoff = ((lane >> 3) & 1) * 8;

    load_stage(0);
    load_stage(1);

    for (int s = 0; s < NSTAGE; s++) {
        if (s + 1 < NSTAGE)
            asm volatile("cp.async.wait_group 1;" ::: "memory");
        else
            asm volatile("cp.async.wait_group 0;" ::: "memory");
        __syncthreads();
        if (s + 2 < NSTAGE) load_stage(s + 2);

        const int buf = s % PIPE;
        const uint32_t ab = aoff0 + buf * BUFB;
        const uint32_t bb = boff0 + buf * BUFB;

#pragma unroll
        for (int ksub = 0; ksub < 2; ksub++) {
            uint32_t af[4][4], bf[2][4];
#pragma unroll
            for (int mt = 0; mt < 4; mt++)
                ldsm_x4(af[mt], ab + (uint32_t)((arow + mt * 16) * SA + ksub * 16 + akoff) * 2);
#pragma unroll
            for (int p = 0; p < 2; p++)
                ldsm_x4(bf[p], bb + (uint32_t)((brow + p * 16) * SA + ksub * 16 + bkoff) * 2);
#pragma unroll
            for (int mt = 0; mt < 4; mt++) {
#pragma unroll
                for (int nt = 0; nt < 4; nt++)
                    mma_f16(acc[mt][nt], af[mt], &bf[nt >> 1][(nt & 1) * 2]);
            }
        }
    }

    const int grp = lane >> 2;
    const int tig = lane & 3;
#pragma unroll
    for (int mt = 0; mt < 4; mt++) {
#pragma unroll
        for (int nt = 0; nt < 4; nt++) {
            const int row = m0 + wm + mt * 16 + grp;
            const int col = n0 + wn + nt * 8 + tig * 2;
            if constexpr (sizeof(OutT) == 2) {
                uint32_t v0 = f2h2(acc[mt][nt][0], acc[mt][nt][1]);
                uint32_t v1 = f2h2(acc[mt][nt][2], acc[mt][nt][3]);
                *(uint32_t*)&C[(size_t)row * Nn + col]       = v0;
                *(uint32_t*)&C[(size_t)(row + 8) * Nn + col] = v1;
            } else {
                float2 v0 = make_float2(acc[mt][nt][0], acc[mt][nt][1]);
                float2 v1 = make_float2(acc[mt][nt][2], acc[mt][nt][3]);
                *(float2*)&C[(size_t)row * Nn + col]       = v0;
                *(float2*)&C[(size_t)(row + 8) * Nn + col] = v1;
            }
        }
    }
}

// ===========================================================================
// Conversion kernels
// ===========================================================================
__global__ __launch_bounds__(256)
void convert_rows(const float* __restrict__ in, __half* __restrict__ out, int total8) {
    int idx = blockIdx.x * 256 + threadIdx.x;
    if (idx >= total8) return;
    const float4 v0 = *(const float4*)(in + idx * 8);
    const float4 v1 = *(const float4*)(in + idx * 8 + 4);
    uint32_t hw[4];
    hw[0] = f2h2(v0.x, v0.y);
    hw[1] = f2h2(v0.z, v0.w);
    hw[2] = f2h2(v1.x, v1.y);
    hw[3] = f2h2(v1.z, v1.w);
    *(uint4*)(out + idx * 8) = *(uint4*)hw;
}

__global__ __launch_bounds__(256)
void transpose_h(const float* __restrict__ W, __half* __restrict__ out, int Nw) {
    __shared__ float t[32][33];
    int n0 = blockIdx.x * 32, k0 = blockIdx.y * 32;
    int tx = threadIdx.x, ty = threadIdx.y;
#pragma unroll
    for (int i = ty; i < 32; i += 8)
        t[i][tx] = W[(size_t)(k0 + i) * Nw + n0 + tx];
    __syncthreads();
#pragma unroll
    for (int i = ty; i < 32; i += 8) {
        int n = n0 + i, k = k0 + tx;
        out[(size_t)n * KPB + k] = __float2half_rn(t[tx][i]);
    }
}

// ===========================================================================
// Attention, fp16 mma; softmax exp via h2exp2 (fp16x2 MUFU) fused into P frags.
// ===========================================================================
#define AT_I 128
#define AT_J 64
#define HSTR 72
#define KBUF (AT_I * HSTR)
#define QBUF (AT_J * HSTR)
#define VBUF (AT_J * HSTR)
#define SMEM_ATTN ((KBUF + 2 * QBUF + 2 * VBUF) * 2)

__global__ __launch_bounds__(256, 2)
void attn_tc(const __half* __restrict__ qkv, __half* __restrict__ Aout) {
    extern __shared__ __half smh[];
    __half* Ksm = smh;

    const uint32_t sbase = smem_u32(smh);
    const uint32_t koff  = sbase;
    const uint32_t q2off = sbase + (uint32_t)KBUF * 2;
    const uint32_t v2off = q2off + (uint32_t)(2 * QBUF) * 2;

    const int it = blockIdx.x;
    const int bh = blockIdx.y;
    const int b = bh >> 4, h = bh & 15;
    const int i0 = it * AT_I;

    const int tid  = threadIdx.x;
    const int wid  = tid >> 5;
    const int lane = tid & 31;
    const int g = lane >> 2;
    const int t = lane & 3;
    const int wm = wid * 16;

    const size_t RS = 3 * DD;
    const __half* Qg = qkv + h * EE;
    const __half* Kg = qkv + DD + h * EE;
    const __half* Vg = qkv + 2 * DD + h * EE;

    const int jt0 = it * 2;
    const int nJT = NN / AT_J;
    const float L2E = 1.4426950408889634f;

    auto prefetch_qv = [&](int jt, int buf) {
        const int j0 = jt * AT_J;
#pragma unroll
        for (int i = 0; i < 2; i++) {
            int idx = i * 256 + tid;
            int r = idx >> 3;
            int c = idx & 7;
            const __half* qsrc = Qg + (size_t)(b * NN + j0 + r) * RS + c * 8;
            const __half* vsrc = Vg + (size_t)(b * NN + j0 + r) * RS + c * 8;
            cp_async16(q2off + (uint32_t)(buf * QBUF + r * HSTR + c * 8) * 2, qsrc);
            cp_async16(v2off + (uint32_t)(buf * VBUF + r * HSTR + c * 8) * 2, vsrc);
        }
        asm volatile("cp.async.commit_group;" ::: "memory");
    };

    prefetch_qv(jt0, 0);

#pragma unroll
    for (int i = 0; i < 4; i++) {
        int idx = i * 256 + tid;
        int r = idx >> 3;
        int c = idx & 7;
        cp_async16(koff + (uint32_t)(r * HSTR + c * 8) * 2,
                   Kg + (size_t)(b * NN + i0 + r) * RS + c * 8);
    }
    asm volatile("cp.async.commit_group;" ::: "memory");

    float m0 = -1e30f, m1 = -1e30f, l0 = 0.0f, l1 = 0.0f;
    float O[8][4];
#pragma unroll
    for (int nt = 0; nt < 8; nt++)
#pragma unroll
        for (int k = 0; k < 4; k++) O[nt][k] = 0.0f;

    const int r0g = i0 + wm + g;
    const int r1g = r0g + 8;

    const int a_row  = wm + (lane & 15);
    const int a_koff = (lane >> 4) * 8;
    const int b_row  = (lane >> 4) * 8 + (lane & 7);
    const int b_koff = ((lane >> 3) & 1) * 8;
    const int v_row  = lane & 15;
    const int v_eoff = (lane >> 4) * 8;

    for (int jt = jt0; jt < nJT; jt++) {
        const int j0 = jt * AT_J;
        const int buf = (jt - jt0) & 1;

        asm volatile("cp.async.wait_group 0;" ::: "memory");
        __syncthreads();
        if (jt + 1 < nJT) prefetch_qv(jt + 1, buf ^ 1);

        const uint32_t qb = q2off + (uint32_t)(buf * QBUF) * 2;
        const uint32_t vb = v2off + (uint32_t)(buf * VBUF) * 2;

        // ---- S = K_i . Q_j ----
        float C[8][4];
#pragma unroll
        for (int nt = 0; nt < 8; nt++)
#pragma unroll
            for (int k = 0; k < 4; k++) C[nt][k] = 0.0f;

#pragma unroll
        for (int kt = 0; kt < 4; kt++) {
            uint32_t af[4];
            ldsm_x4(af, koff + (uint32_t)(a_row * HSTR + kt * 16 + a_koff) * 2);
            uint32_t qf[4][4];
#pragma unroll
            for (int p = 0; p < 4; p++)
                ldsm_x4(qf[p], qb + (uint32_t)((p * 16 + b_row) * HSTR + kt * 16 + b_koff) * 2);
#pragma unroll
            for (int nt = 0; nt < 8; nt++)
                mma_f16(C[nt], af, &qf[nt >> 1][(nt & 1) * 2]);
        }

        // ---- scale + mask + row max ----
        const bool needmask = (j0 < i0 + AT_I);
        float rmax0 = -1e30f, rmax1 = -1e30f;
#pragma unroll
        for (int nt = 0; nt < 8; nt++) {
            C[nt][0] *= 0.125f; C[nt][1] *= 0.125f;
            C[nt][2] *= 0.125f; C[nt][3] *= 0.125f;
            if (needmask) {
                int c0 = j0 + nt * 8 + 2 * t;
                int c1 = c0 + 1;
                if (c0 < r0g) C[nt][0] = -1e30f;
                if (c1 < r0g) C[nt][1] = -1e30f;
                if (c0 < r1g) C[nt][2] = -1e30f;
                if (c1 < r1g) C[nt][3] = -1e30f;
            }
            rmax0 = fmaxf(rmax0, fmaxf(C[nt][0], C[nt][1]));
            rmax1 = fmaxf(rmax1, fmaxf(C[nt][2], C[nt][3]));
        }
        rmax0 = fmaxf(rmax0, __shfl_xor_sync(0xffffffffu, rmax0, 1));
        rmax0 = fmaxf(rmax0, __shfl_xor_sync(0xffffffffu, rmax0, 2));
        rmax1 = fmaxf(rmax1, __shfl_xor_sync(0xffffffffu, rmax1, 1));
        rmax1 = fmaxf(rmax1, __shfl_xor_sync(0xffffffffu, rmax1, 2));

        float mn0 = fmaxf(m0, rmax0), mn1 = fmaxf(m1, rmax1);
        float sc0 = __expf(m0 - mn0), sc1 = __expf(m1 - mn1);
        m0 = mn0; m1 = mn1;

        // ---- exp via h2exp2, building the PV A-fragments directly ----
        uint32_t P[4][4];
        float rs0 = 0.0f, rs1 = 0.0f;
#pragma unroll
        for (int kt = 0; kt < 4; kt++) {
            __half2 p0 = h2exp2(__floats2half2_rn((C[2*kt][0]   - mn0) * L2E,
                                                  (C[2*kt][1]   - mn0) * L2E));
            __half2 p1 = h2exp2(__floats2half2_rn((C[2*kt][2]   - mn1) * L2E,
                                                  (C[2*kt][3]   - mn1) * L2E));
            __half2 p2 = h2exp2(__floats2half2_rn((C[2*kt+1][0] - mn0) * L2E,
                                                  (C[2*kt+1][1] - mn0) * L2E));
            __half2 p3 = h2exp2(__floats2half2_rn((C[2*kt+1][2] - mn1) * L2E,
                                                  (C[2*kt+1][3] - mn1) * L2E));
            P[kt][0] = h2u(p0); P[kt][1] = h2u(p1);
            P[kt][2] = h2u(p2); P[kt][3] = h2u(p3);
            float2 f0 = __half22float2(p0), f2v = __half22float2(p2);
            float2 f1 = __half22float2(p1), f3v = __half22float2(p3);
            rs0 += (f0.x + f0.y) + (f2v.x + f2v.y);
            rs1 += (f1.x + f1.y) + (f3v.x + f3v.y);
        }
        rs0 += __shfl_xor_sync(0xffffffffu, rs0, 1);
        rs0 += __shfl_xor_sync(0xffffffffu, rs0, 2);
        rs1 += __shfl_xor_sync(0xffffffffu, rs1, 1);
        rs1 += __shfl_xor_sync(0xffffffffu, rs1, 2);
        l0 = l0 * sc0 + rs0;
        l1 = l1 * sc1 + rs1;
#pragma unroll
        for (int nt = 0; nt < 8; nt++) {
            O[nt][0] *= sc0; O[nt][1] *= sc0;
            O[nt][2] *= sc1; O[nt][3] *= sc1;
        }

        // ---- O += P @ V ----
#pragma unroll
        for (int kt = 0; kt < 4; kt++) {
#pragma unroll
            for (int e0 = 0; e0 < 64; e0 += 16) {
                uint32_t vf[4];
                ldsm_x4_t(vf, vb + (uint32_t)((kt * 16 + v_row) * HSTR + e0 + v_eoff) * 2);
                mma_f16(O[e0 >> 3],       P[kt], &vf[0]);
                mma_f16(O[(e0 >> 3) + 1], P[kt], &vf[2]);
            }
        }
        __syncthreads();
    }

    // ---- fused epilogue: stage fp16 O in Ksm, coalesced uint4 stores ----
    {
        float inv0 = 1.0f / l0, inv1 = 1.0f / l1;
#pragma unroll
        for (int nt = 0; nt < 8; nt++) {
            int col = nt * 8 + 2 * t;
            *(uint32_t*)&Ksm[(wm + g)     * HSTR + col] = f2h2(O[nt][0] * inv0, O[nt][1] * inv0);
            *(uint32_t*)&Ksm[(wm + g + 8) * HSTR + col] = f2h2(O[nt][2] * inv1, O[nt][3] * inv1);
        }
    }
    __syncthreads();

#pragma unroll
    for (int itr = 0; itr < 4; itr++) {
        int idx = itr * 256 + tid;
        int r  = idx >> 3;
        int c8 = (idx & 7) << 3;
        uint4 v = *(const uint4*)&Ksm[r * HSTR + c8];
        __half* dst = Aout + (size_t)(b * NN + i0 + r) * KPA + h * EE + c8;
        *(uint4*)dst = v;
    }
}

// ===========================================================================
extern "C" void kernel_launch(void* const* d_in, const int* in_sizes, int n_in,
                              void* d_out, int out_size) {
    const float* x    = (const float*)d_in[0];
    const float* Wqkv = (const float*)d_in[1];
    const float* Wo   = (const float*)d_in[2];
    float* out = (float*)d_out;

    __half* qkv = nullptr;
    __half* Abuf = nullptr;  __half* Bbuf = nullptr;
    cudaGetSymbolAddress((void**)&qkv,  g_qkv);
    cudaGetSymbolAddress((void**)&Abuf, g_A);
    cudaGetSymbolAddress((void**)&Bbuf, g_B);

    cudaFuncSetAttribute(gemm_hmma<__half>, cudaFuncAttributeMaxDynamicSharedMemorySize, SMEM_GEMM);
    cudaFuncSetAttribute(gemm_hmma<float>,  cudaFuncAttributeMaxDynamicSharedMemorySize, SMEM_GEMM);
    cudaFuncSetAttribute(attn_tc, cudaFuncAttributeMaxDynamicSharedMemorySize, SMEM_ATTN);

    // 1) x -> A' fp16 (vectorized)
    convert_rows<<<(MTOT * DD / 8 + 255) / 256, 256>>>(x, Abuf, MTOT * DD / 8);
    // 2) W_qkv -> B' fp16 transpose
    transpose_h<<<dim3(3 * DD / 32, DD / 32), dim3(32, 8)>>>(Wqkv, Bbuf, 3 * DD);
    // 3) QKV GEMM -> fp16 qkv
    gemm_hmma<__half><<<dim3(3 * DD / 128, MTOT / 128), 256, SMEM_GEMM>>>(Abuf, Bbuf, qkv, MTOT, 3 * DD);
    // 4) attention (fp16 mma, h2exp2 softmax) -> fp16 A'
    attn_tc<<<dim3(NN / AT_I, BB * HH), 256, SMEM_ATTN>>>(qkv, Abuf);
    // 5) W_o -> B'
    transpose_h<<<dim3(DD / 32, DD / 32), dim3(32, 8)>>>(Wo, Bbuf, DD);
    // 6) O-proj GEMM -> f32 out
    gemm_hmma<float><<<dim3(DD / 128, MTOT / 128), 256, SMEM_GEMM>>>(Abuf, Bbuf, out, MTOT, DD);
}

// round 17
// speedup vs baseline: 1.1515x; 1.0974x over previous
#include <cuda_runtime.h>
#include <cuda_fp16.h>
#include <cstdint>
#include <math.h>

// ---------------------------------------------------------------------------
// Problem: x[4,2048,1024] f32; W_qkv[1024,3072]; W_o[1024,1024]; out[4,2048,1024]
//   1) ONE prep kernel: x->A' fp16, W_qkv->B' fp16 (transposed),
//                       W_o->B'[3M..] fp16 (transposed)
//   2) HMMA fp16 GEMM (R14 config) -> g_qkv (fp16)
//   3) fp16 mma attention (LPT grid order) -> fp16 A'
//   4) HMMA fp16 GEMM -> out (f32)
// ---------------------------------------------------------------------------
#define BB 4
#define NN 2048
#define DD 1024
#define HH 16
#define EE 64
#define MTOT (BB * NN)   // 8192
#define KPA  1024
#define KPB  1024
#define SA   40          // gemm smem row stride in fp16 (32 data + 8 pad)
#define NSTAGE 32        // KPA / 32
#define PIPE 3
#define WO_OFF (3 * DD * KPB)   // offset of W_o' inside g_B

__device__ __half g_qkv[MTOT * 3 * DD];
__device__ __half g_A[MTOT * KPA];
__device__ __half g_B[4 * DD * KPB];     // [0,3M): W_qkv'  [3M,4M): W_o'

// ===========================================================================
__device__ __forceinline__ uint32_t smem_u32(const void* p) {
    uint32_t a;
    asm("{ .reg .u64 t; cvta.to.shared.u64 t, %1; cvt.u32.u64 %0, t; }"
        : "=r"(a) : "l"(p));
    return a;
}
__device__ __forceinline__ void cp_async16(uint32_t dst, const void* src) {
    asm volatile("cp.async.cg.shared.global [%0], [%1], 16;"
                 :: "r"(dst), "l"(src) : "memory");
}
__device__ __forceinline__ void ldsm_x4(uint32_t* r, uint32_t addr) {
    asm volatile("ldmatrix.sync.aligned.m8n8.x4.shared.b16 {%0,%1,%2,%3}, [%4];"
                 : "=r"(r[0]), "=r"(r[1]), "=r"(r[2]), "=r"(r[3]) : "r"(addr));
}
__device__ __forceinline__ void ldsm_x4_t(uint32_t* r, uint32_t addr) {
    asm volatile("ldmatrix.sync.aligned.m8n8.x4.trans.shared.b16 {%0,%1,%2,%3}, [%4];"
                 : "=r"(r[0]), "=r"(r[1]), "=r"(r[2]), "=r"(r[3]) : "r"(addr));
}
__device__ __forceinline__ void mma_f16(float* d, const uint32_t* a, const uint32_t* b) {
    asm volatile(
        "mma.sync.aligned.m16n8k16.row.col.f32.f16.f16.f32 "
        "{%0,%1,%2,%3}, {%4,%5,%6,%7}, {%8,%9}, {%0,%1,%2,%3};"
        : "+f"(d[0]), "+f"(d[1]), "+f"(d[2]), "+f"(d[3])
        : "r"(a[0]), "r"(a[1]), "r"(a[2]), "r"(a[3]), "r"(b[0]), "r"(b[1]));
}
__device__ __forceinline__ uint32_t f2h2(float lo, float hi) {
    __half2 p = __floats2half2_rn(lo, hi);
    return *reinterpret_cast<uint32_t*>(&p);
}
__device__ __forceinline__ uint32_t h2u(__half2 p) {
    return *reinterpret_cast<uint32_t*>(&p);
}

// ===========================================================================
// HMMA fp16 GEMM — exact R14 config (BK=32, 3-stage cp.async, 8 warps 64x32)
// ===========================================================================
#define BUFB (128 * SA * 2)
#define SMEM_GEMM (PIPE * 2 * BUFB)

template <typename OutT>
__global__ __launch_bounds__(256, 2)
void gemm_hmma(const __half* __restrict__ A,
               const __half* __restrict__ B,
               OutT* __restrict__ C, int M, int Nn) {
    extern __shared__ __half smhf[];
    const int tid  = threadIdx.x;
    const int wid  = tid >> 5;
    const int lane = tid & 31;
    const int m0 = blockIdx.y * 128;
    const int n0 = blockIdx.x * 128;
    const int wm = (wid >> 2) * 64;
    const int wn = (wid & 3) * 32;

    const uint32_t sbase = smem_u32(smhf);
    const uint32_t aoff0 = sbase;
    const uint32_t boff0 = sbase + PIPE * BUFB;

    const __half* Ag = A + (size_t)m0 * KPA;
    const __half* Bg = B + (size_t)n0 * KPB;

    const int lr  = tid >> 1;
    const int lkc = (tid & 1) * 2;

    auto load_stage = [&](int s) {
        const int buf = s % PIPE;
        const uint32_t ab = aoff0 + buf * BUFB;
        const uint32_t bb = boff0 + buf * BUFB;
        const int k0 = s * 32;
#pragma unroll
        for (int j = 0; j < 2; j++) {
            const int kc = lkc + j;
            const uint32_t doff = (uint32_t)(lr * SA + kc * 8) * 2;
            cp_async16(ab + doff, Ag + (size_t)lr * KPA + k0 + kc * 8);
            cp_async16(bb + doff, Bg + (size_t)lr * KPB + k0 + kc * 8);
        }
        asm volatile("cp.async.commit_group;" ::: "memory");
    };

    float acc[4][4][4];
#pragma unroll
    for (int i = 0; i < 4; i++)
#pragma unroll
        for (int j = 0; j < 4; j++)
#pragma unroll
            for (int k = 0; k < 4; k++) acc[i][j][k] = 0.0f;

    const int arow  = wm + (lane & 15);
    const int akoff = (lane >> 4) * 8;
    const int brow  = wn + (lane >> 4) * 8 + (lane & 7);
    const int bkoff = ((lane >> 3) & 1) * 8;

    load_stage(0);
    load_stage(1);

    for (int s = 0; s < NSTAGE; s++) {
        if (s + 1 < NSTAGE)
            asm volatile("cp.async.wait_group 1;" ::: "memory");
        else
            asm volatile("cp.async.wait_group 0;" ::: "memory");
        __syncthreads();
        if (s + 2 < NSTAGE) load_stage(s + 2);

        const int buf = s % PIPE;
        const uint32_t ab = aoff0 + buf * BUFB;
        const uint32_t bb = boff0 + buf * BUFB;

#pragma unroll
        for (int ksub = 0; ksub < 2; ksub++) {
            uint32_t af[4][4], bf[2][4];
#pragma unroll
            for (int mt = 0; mt < 4; mt++)
                ldsm_x4(af[mt], ab + (uint32_t)((arow + mt * 16) * SA + ksub * 16 + akoff) * 2);
#pragma unroll
            for (int p = 0; p < 2; p++)
                ldsm_x4(bf[p], bb + (uint32_t)((brow + p * 16) * SA + ksub * 16 + bkoff) * 2);
#pragma unroll
            for (int mt = 0; mt < 4; mt++) {
#pragma unroll
                for (int nt = 0; nt < 4; nt++)
                    mma_f16(acc[mt][nt], af[mt], &bf[nt >> 1][(nt & 1) * 2]);
            }
        }
    }

    const int grp = lane >> 2;
    const int tig = lane & 3;
#pragma unroll
    for (int mt = 0; mt < 4; mt++) {
#pragma unroll
        for (int nt = 0; nt < 4; nt++) {
            const int row = m0 + wm + mt * 16 + grp;
            const int col = n0 + wn + nt * 8 + tig * 2;
            if constexpr (sizeof(OutT) == 2) {
                uint32_t v0 = f2h2(acc[mt][nt][0], acc[mt][nt][1]);
                uint32_t v1 = f2h2(acc[mt][nt][2], acc[mt][nt][3]);
                *(uint32_t*)&C[(size_t)row * Nn + col]       = v0;
                *(uint32_t*)&C[(size_t)(row + 8) * Nn + col] = v1;
            } else {
                float2 v0 = make_float2(acc[mt][nt][0], acc[mt][nt][1]);
                float2 v1 = make_float2(acc[mt][nt][2], acc[mt][nt][3]);
                *(float2*)&C[(size_t)row * Nn + col]       = v0;
                *(float2*)&C[(size_t)(row + 8) * Nn + col] = v1;
            }
        }
    }
}

// ===========================================================================
// Merged prep kernel: convert x (8 elem/thread) + transpose W_qkv + W_o.
// grid.x = 4096 (convert) + 3072 (Wqkv tiles) + 1024 (Wo tiles) = 8192
// ===========================================================================
#define PREP_CONVERT_BLOCKS 4096
#define PREP_WQKV_BLOCKS    3072
#define PREP_TOTAL_BLOCKS   8192

__global__ __launch_bounds__(256)
void prep_all(const float* __restrict__ x, const float* __restrict__ Wqkv,
              const float* __restrict__ Wo,
              __half* __restrict__ A, __half* __restrict__ B) {
    const int blk = blockIdx.x;
    const int tid = threadIdx.x;

    if (blk < PREP_CONVERT_BLOCKS) {
        // x -> A' fp16, 8 elems/thread
        int idx = blk * 256 + tid;
        const float4 v0 = *(const float4*)(x + (size_t)idx * 8);
        const float4 v1 = *(const float4*)(x + (size_t)idx * 8 + 4);
        uint32_t hw[4];
        hw[0] = f2h2(v0.x, v0.y);
        hw[1] = f2h2(v0.z, v0.w);
        hw[2] = f2h2(v1.x, v1.y);
        hw[3] = f2h2(v1.z, v1.w);
        *(uint4*)(A + (size_t)idx * 8) = *(uint4*)hw;
        return;
    }

    // transpose a 32x32 tile of W (f32 [K, Nw]) into B' (fp16 [Nw, 1024])
    __shared__ float tsm[32][33];
    const float* W;
    __half* dst;
    int Nw, tile;
    if (blk < PREP_CONVERT_BLOCKS + PREP_WQKV_BLOCKS) {
        tile = blk - PREP_CONVERT_BLOCKS;
        W = Wqkv; dst = B; Nw = 3 * DD;
    } else {
        tile = blk - PREP_CONVERT_BLOCKS - PREP_WQKV_BLOCKS;
        W = Wo; dst = B + WO_OFF; Nw = DD;
    }
    const int ntx = Nw / 32;           // tiles along n
    const int n0 = (tile % ntx) * 32;
    const int k0 = (tile / ntx) * 32;
    const int tx = tid & 31;
    const int ty = tid >> 5;           // 0..7
#pragma unroll
    for (int i = ty; i < 32; i += 8)
        tsm[i][tx] = W[(size_t)(k0 + i) * Nw + n0 + tx];
    __syncthreads();
#pragma unroll
    for (int i = ty; i < 32; i += 8) {
        int n = n0 + i, k = k0 + tx;
        dst[(size_t)n * KPB + k] = __float2half_rn(tsm[tx][i]);
    }
}

// ===========================================================================
// Attention — R16 kernel, LPT grid order (x=bh, y=it; heavy it=0 first)
// ===========================================================================
#define AT_I 128
#define AT_J 64
#define HSTR 72
#define KBUF (AT_I * HSTR)
#define QBUF (AT_J * HSTR)
#define VBUF (AT_J * HSTR)
#define SMEM_ATTN ((KBUF + 2 * QBUF + 2 * VBUF) * 2)

__global__ __launch_bounds__(256, 2)
void attn_tc(const __half* __restrict__ qkv, __half* __restrict__ Aout) {
    extern __shared__ __half smh[];
    __half* Ksm = smh;

    const uint32_t sbase = smem_u32(smh);
    const uint32_t koff  = sbase;
    const uint32_t q2off = sbase + (uint32_t)KBUF * 2;
    const uint32_t v2off = q2off + (uint32_t)(2 * QBUF) * 2;

    const int it = blockIdx.y;          // LPT: heavy tiles (small it) first
    const int bh = blockIdx.x;
    const int b = bh >> 4, h = bh & 15;
    const int i0 = it * AT_I;

    const int tid  = threadIdx.x;
    const int wid  = tid >> 5;
    const int lane = tid & 31;
    const int g = lane >> 2;
    const int t = lane & 3;
    const int wm = wid * 16;

    const size_t RS = 3 * DD;
    const __half* Qg = qkv + h * EE;
    const __half* Kg = qkv + DD + h * EE;
    const __half* Vg = qkv + 2 * DD + h * EE;

    const int jt0 = it * 2;
    const int nJT = NN / AT_J;
    const float L2E = 1.4426950408889634f;

    auto prefetch_qv = [&](int jt, int buf) {
        const int j0 = jt * AT_J;
#pragma unroll
        for (int i = 0; i < 2; i++) {
            int idx = i * 256 + tid;
            int r = idx >> 3;
            int c = idx & 7;
            const __half* qsrc = Qg + (size_t)(b * NN + j0 + r) * RS + c * 8;
            const __half* vsrc = Vg + (size_t)(b * NN + j0 + r) * RS + c * 8;
            cp_async16(q2off + (uint32_t)(buf * QBUF + r * HSTR + c * 8) * 2, qsrc);
            cp_async16(v2off + (uint32_t)(buf * VBUF + r * HSTR + c * 8) * 2, vsrc);
        }
        asm volatile("cp.async.commit_group;" ::: "memory");
    };

    prefetch_qv(jt0, 0);

#pragma unroll
    for (int i = 0; i < 4; i++) {
        int idx = i * 256 + tid;
        int r = idx >> 3;
        int c = idx & 7;
        cp_async16(koff + (uint32_t)(r * HSTR + c * 8) * 2,
                   Kg + (size_t)(b * NN + i0 + r) * RS + c * 8);
    }
    asm volatile("cp.async.commit_group;" ::: "memory");

    float m0 = -1e30f, m1 = -1e30f, l0 = 0.0f, l1 = 0.0f;
    float O[8][4];
#pragma unroll
    for (int nt = 0; nt < 8; nt++)
#pragma unroll
        for (int k = 0; k < 4; k++) O[nt][k] = 0.0f;

    const int r0g = i0 + wm + g;
    const int r1g = r0g + 8;

    const int a_row  = wm + (lane & 15);
    const int a_koff = (lane >> 4) * 8;
    const int b_row  = (lane >> 4) * 8 + (lane & 7);
    const int b_koff = ((lane >> 3) & 1) * 8;
    const int v_row  = lane & 15;
    const int v_eoff = (lane >> 4) * 8;

    for (int jt = jt0; jt < nJT; jt++) {
        const int j0 = jt * AT_J;
        const int buf = (jt - jt0) & 1;

        asm volatile("cp.async.wait_group 0;" ::: "memory");
        __syncthreads();
        if (jt + 1 < nJT) prefetch_qv(jt + 1, buf ^ 1);

        const uint32_t qb = q2off + (uint32_t)(buf * QBUF) * 2;
        const uint32_t vb = v2off + (uint32_t)(buf * VBUF) * 2;

        // ---- S = K_i . Q_j ----
        float C[8][4];
#pragma unroll
        for (int nt = 0; nt < 8; nt++)
#pragma unroll
            for (int k = 0; k < 4; k++) C[nt][k] = 0.0f;

#pragma unroll
        for (int kt = 0; kt < 4; kt++) {
            uint32_t af[4];
            ldsm_x4(af, koff + (uint32_t)(a_row * HSTR + kt * 16 + a_koff) * 2);
            uint32_t qf[4][4];
#pragma unroll
            for (int p = 0; p < 4; p++)
                ldsm_x4(qf[p], qb + (uint32_t)((p * 16 + b_row) * HSTR + kt * 16 + b_koff) * 2);
#pragma unroll
            for (int nt = 0; nt < 8; nt++)
                mma_f16(C[nt], af, &qf[nt >> 1][(nt & 1) * 2]);
        }

        // ---- scale + mask + row max ----
        const bool needmask = (j0 < i0 + AT_I);
        float rmax0 = -1e30f, rmax1 = -1e30f;
#pragma unroll
        for (int nt = 0; nt < 8; nt++) {
            C[nt][0] *= 0.125f; C[nt][1] *= 0.125f;
            C[nt][2] *= 0.125f; C[nt][3] *= 0.125f;
            if (needmask) {
                int c0 = j0 + nt * 8 + 2 * t;
                int c1 = c0 + 1;
                if (c0 < r0g) C[nt][0] = -1e30f;
                if (c1 < r0g) C[nt][1] = -1e30f;
                if (c0 < r1g) C[nt][2] = -1e30f;
                if (c1 < r1g) C[nt][3] = -1e30f;
            }
            rmax0 = fmaxf(rmax0, fmaxf(C[nt][0], C[nt][1]));
            rmax1 = fmaxf(rmax1, fmaxf(C[nt][2], C[nt][3]));
        }
        rmax0 = fmaxf(rmax0, __shfl_xor_sync(0xffffffffu, rmax0, 1));
        rmax0 = fmaxf(rmax0, __shfl_xor_sync(0xffffffffu, rmax0, 2));
        rmax1 = fmaxf(rmax1, __shfl_xor_sync(0xffffffffu, rmax1, 1));
        rmax1 = fmaxf(rmax1, __shfl_xor_sync(0xffffffffu, rmax1, 2));

        float mn0 = fmaxf(m0, rmax0), mn1 = fmaxf(m1, rmax1);
        float sc0 = __expf(m0 - mn0), sc1 = __expf(m1 - mn1);
        m0 = mn0; m1 = mn1;

        // ---- exp via h2exp2, building the PV A-fragments directly ----
        uint32_t P[4][4];
        float rs0 = 0.0f, rs1 = 0.0f;
#pragma unroll
        for (int kt = 0; kt < 4; kt++) {
            __half2 p0 = h2exp2(__floats2half2_rn((C[2*kt][0]   - mn0) * L2E,
                                                  (C[2*kt][1]   - mn0) * L2E));
            __half2 p1 = h2exp2(__floats2half2_rn((C[2*kt][2]   - mn1) * L2E,
                                                  (C[2*kt][3]   - mn1) * L2E));
            __half2 p2 = h2exp2(__floats2half2_rn((C[2*kt+1][0] - mn0) * L2E,
                                                  (C[2*kt+1][1] - mn0) * L2E));
            __half2 p3 = h2exp2(__floats2half2_rn((C[2*kt+1][2] - mn1) * L2E,
                                                  (C[2*kt+1][3] - mn1) * L2E));
            P[kt][0] = h2u(p0); P[kt][1] = h2u(p1);
            P[kt][2] = h2u(p2); P[kt][3] = h2u(p3);
            float2 f0 = __half22float2(p0), f2v = __half22float2(p2);
            float2 f1 = __half22float2(p1), f3v = __half22float2(p3);
            rs0 += (f0.x + f0.y) + (f2v.x + f2v.y);
            rs1 += (f1.x + f1.y) + (f3v.x + f3v.y);
        }
        rs0 += __shfl_xor_sync(0xffffffffu, rs0, 1);
        rs0 += __shfl_xor_sync(0xffffffffu, rs0, 2);
        rs1 += __shfl_xor_sync(0xffffffffu, rs1, 1);
        rs1 += __shfl_xor_sync(0xffffffffu, rs1, 2);
        l0 = l0 * sc0 + rs0;
        l1 = l1 * sc1 + rs1;
#pragma unroll
        for (int nt = 0; nt < 8; nt++) {
            O[nt][0] *= sc0; O[nt][1] *= sc0;
            O[nt][2] *= sc1; O[nt][3] *= sc1;
        }

        // ---- O += P @ V ----
#pragma unroll
        for (int kt = 0; kt < 4; kt++) {
#pragma unroll
            for (int e0 = 0; e0 < 64; e0 += 16) {
                uint32_t vf[4];
                ldsm_x4_t(vf, vb + (uint32_t)((kt * 16 + v_row) * HSTR + e0 + v_eoff) * 2);
                mma_f16(O[e0 >> 3],       P[kt], &vf[0]);
                mma_f16(O[(e0 >> 3) + 1], P[kt], &vf[2]);
            }
        }
        __syncthreads();
    }

    // ---- fused epilogue: stage fp16 O in Ksm, coalesced uint4 stores ----
    {
        float inv0 = 1.0f / l0, inv1 = 1.0f / l1;
#pragma unroll
        for (int nt = 0; nt < 8; nt++) {
            int col = nt * 8 + 2 * t;
            *(uint32_t*)&Ksm[(wm + g)     * HSTR + col] = f2h2(O[nt][0] * inv0, O[nt][1] * inv0);
            *(uint32_t*)&Ksm[(wm + g + 8) * HSTR + col] = f2h2(O[nt][2] * inv1, O[nt][3] * inv1);
        }
    }
    __syncthreads();

#pragma unroll
    for (int itr = 0; itr < 4; itr++) {
        int idx = itr * 256 + tid;
        int r  = idx >> 3;
        int c8 = (idx & 7) << 3;
        uint4 v = *(const uint4*)&Ksm[r * HSTR + c8];
        __half* dst = Aout + (size_t)(b * NN + i0 + r) * KPA + h * EE + c8;
        *(uint4*)dst = v;
    }
}

// ===========================================================================
extern "C" void kernel_launch(void* const* d_in, const int* in_sizes, int n_in,
                              void* d_out, int out_size) {
    const float* x    = (const float*)d_in[0];
    const float* Wqkv = (const float*)d_in[1];
    const float* Wo   = (const float*)d_in[2];
    float* out = (float*)d_out;

    __half* qkv = nullptr;
    __half* Abuf = nullptr;  __half* Bbuf = nullptr;
    cudaGetSymbolAddress((void**)&qkv,  g_qkv);
    cudaGetSymbolAddress((void**)&Abuf, g_A);
    cudaGetSymbolAddress((void**)&Bbuf, g_B);

    cudaFuncSetAttribute(gemm_hmma<__half>, cudaFuncAttributeMaxDynamicSharedMemorySize, SMEM_GEMM);
    cudaFuncSetAttribute(gemm_hmma<float>,  cudaFuncAttributeMaxDynamicSharedMemorySize, SMEM_GEMM);
    cudaFuncSetAttribute(attn_tc, cudaFuncAttributeMaxDynamicSharedMemorySize, SMEM_ATTN);

    // 1) merged prep: x->A', Wqkv->B'[0..3M), Wo->B'[3M..4M)
    prep_all<<<PREP_TOTAL_BLOCKS, 256>>>(x, Wqkv, Wo, Abuf, Bbuf);
    // 2) QKV GEMM -> fp16 qkv
    gemm_hmma<__half><<<dim3(3 * DD / 128, MTOT / 128), 256, SMEM_GEMM>>>(Abuf, Bbuf, qkv, MTOT, 3 * DD);
    // 3) attention (LPT order) -> fp16 A'
    attn_tc<<<dim3(BB * HH, NN / AT_I), 256, SMEM_ATTN>>>(qkv, Abuf);
    // 4) O-proj GEMM -> f32 out
    gemm_hmma<float><<<dim3(DD / 128, MTOT / 128), 256, SMEM_GEMM>>>(Abuf, Bbuf + WO_OFF, out, MTOT, DD);
}